// round 2
// baseline (speedup 1.0000x reference)
#include <cuda_runtime.h>
#include <cstdint>

// ---------------------------------------------------------------------------
// AdjGenerator: adj = (mean_h sigmoid(log(relu(Wg·PE)+1e-6) + (q·kT)/32) > 0.5)
// N = M = 2048, D = 1024, EMB = 64, HEADS = 16
//
// Stage 1: q = ref @ WqT + bq   (fp32 SGEMM-NT, packed f32x2 FFMA2)
// Stage 2: k = sup @ WkT + bk
// Stage 3: aff = (q @ kT) * (1/32)
// Stage 4: stream PE, accumulate 16 head gates, fused sigmoid-mean-threshold
// ---------------------------------------------------------------------------

#define NDIM 2048
#define MDIM 2048
#define DDIM 1024
#define EMB  64
#define HEADS 16

// Scratch (no cudaMalloc allowed) — 8 + 8 + 16 MB
__device__ float g_q[NDIM * DDIM];
__device__ float g_k[MDIM * DDIM];
__device__ float g_aff[NDIM * MDIM];

typedef unsigned long long ull;

// ---- packed f32x2 helpers (Blackwell FFMA2 path, PTX-only) ----------------
__device__ __forceinline__ ull dup2(float v) {
    ull r;
    asm("mov.b64 %0, {%1, %1};" : "=l"(r) : "f"(v));
    return r;
}
__device__ __forceinline__ void fma2(ull& d, ull a, ull b) {
    asm("fma.rn.f32x2 %0, %1, %2, %0;" : "+l"(d) : "l"(a), "l"(b));
}
__device__ __forceinline__ float2 unpack2(ull v) {
    float2 f;
    asm("mov.b64 {%0, %1}, %2;" : "=f"(f.x), "=f"(f.y) : "l"(v));
    return f;
}

// ---------------------------------------------------------------------------
// SGEMM NT: C[r,c] = scale * sum_d A[r,d]*B[c,d] + bias[c]
// BM=BN=128, BK=16, 256 threads, 8x8 per thread, accumulators packed f32x2.
// outsel: 0 -> C=g_q, 1 -> C=g_k, 2 -> A=g_q,B=g_k,C=g_aff
// K fixed at 1024. All dims divide tiles exactly; no bounds checks.
// ---------------------------------------------------------------------------
#define BM 128
#define BN 128
#define BK 16

__global__ void __launch_bounds__(256)
gemm_nt_kernel(const float* __restrict__ A, const float* __restrict__ B,
               const float* __restrict__ bias, int Ncols, float scale, int outsel)
{
    float* C;
    if (outsel == 0)      C = g_q;
    else if (outsel == 1) C = g_k;
    else { C = g_aff; A = g_q; B = g_k; }

    const int K = DDIM;

    __shared__ float As[BK][BM + 4];
    __shared__ float Bs[BK][BN + 4];

    const int tid = threadIdx.x;
    const int tx = tid & 15;        // 0..15  -> col block of 8
    const int ty = tid >> 4;        // 0..15  -> row block of 8
    const int row0 = blockIdx.y * BM;
    const int col0 = blockIdx.x * BN;

    const float* Abase = A + (size_t)row0 * K;
    const float* Bbase = B + (size_t)col0 * K;

    // load-slot mapping: 512 float4 slots per operand, 2 per thread
    const int ar0 = tid >> 2,          ac0 = (tid & 3) * 4;
    const int ar1 = (tid + 256) >> 2,  ac1 = ((tid + 256) & 3) * 4;

    // prologue: chunk 0 global->smem
    float4 av0 = *(const float4*)&Abase[(size_t)ar0 * K + ac0];
    float4 av1 = *(const float4*)&Abase[(size_t)ar1 * K + ac1];
    float4 bv0 = *(const float4*)&Bbase[(size_t)ar0 * K + ac0];
    float4 bv1 = *(const float4*)&Bbase[(size_t)ar1 * K + ac1];

    As[(ac0 >> 2) * 4 + 0][ar0] = av0.x; As[(ac0 >> 2) * 4 + 1][ar0] = av0.y;
    As[(ac0 >> 2) * 4 + 2][ar0] = av0.z; As[(ac0 >> 2) * 4 + 3][ar0] = av0.w;
    As[(ac1 >> 2) * 4 + 0][ar1] = av1.x; As[(ac1 >> 2) * 4 + 1][ar1] = av1.y;
    As[(ac1 >> 2) * 4 + 2][ar1] = av1.z; As[(ac1 >> 2) * 4 + 3][ar1] = av1.w;
    Bs[(ac0 >> 2) * 4 + 0][ar0] = bv0.x; Bs[(ac0 >> 2) * 4 + 1][ar0] = bv0.y;
    Bs[(ac0 >> 2) * 4 + 2][ar0] = bv0.z; Bs[(ac0 >> 2) * 4 + 3][ar0] = bv0.w;
    Bs[(ac1 >> 2) * 4 + 0][ar1] = bv1.x; Bs[(ac1 >> 2) * 4 + 1][ar1] = bv1.y;
    Bs[(ac1 >> 2) * 4 + 2][ar1] = bv1.z; Bs[(ac1 >> 2) * 4 + 3][ar1] = bv1.w;
    __syncthreads();

    ull c2[8][4];
#pragma unroll
    for (int i = 0; i < 8; i++)
#pragma unroll
        for (int j = 0; j < 4; j++) c2[i][j] = 0ull;

    for (int kc = BK; kc <= K; kc += BK) {
        // prefetch next chunk into registers
        if (kc < K) {
            av0 = *(const float4*)&Abase[(size_t)ar0 * K + kc + ac0];
            av1 = *(const float4*)&Abase[(size_t)ar1 * K + kc + ac1];
            bv0 = *(const float4*)&Bbase[(size_t)ar0 * K + kc + ac0];
            bv1 = *(const float4*)&Bbase[(size_t)ar1 * K + kc + ac1];
        }
        // compute current chunk
#pragma unroll
        for (int k = 0; k < BK; k++) {
            float4 aA = *(const float4*)&As[k][ty * 8];
            float4 aB = *(const float4*)&As[k][ty * 8 + 4];
            ull a2[8];
            a2[0] = dup2(aA.x); a2[1] = dup2(aA.y); a2[2] = dup2(aA.z); a2[3] = dup2(aA.w);
            a2[4] = dup2(aB.x); a2[5] = dup2(aB.y); a2[6] = dup2(aB.z); a2[7] = dup2(aB.w);
            ulonglong2 b01 = *(const ulonglong2*)&Bs[k][tx * 8];
            ulonglong2 b23 = *(const ulonglong2*)&Bs[k][tx * 8 + 4];
            ull b2[4] = { b01.x, b01.y, b23.x, b23.y };
#pragma unroll
            for (int i = 0; i < 8; i++) {
#pragma unroll
                for (int j = 0; j < 4; j++) fma2(c2[i][j], a2[i], b2[j]);
            }
        }
        if (kc < K) {
            __syncthreads();
            As[(ac0 >> 2) * 4 + 0][ar0] = av0.x; As[(ac0 >> 2) * 4 + 1][ar0] = av0.y;
            As[(ac0 >> 2) * 4 + 2][ar0] = av0.z; As[(ac0 >> 2) * 4 + 3][ar0] = av0.w;
            As[(ac1 >> 2) * 4 + 0][ar1] = av1.x; As[(ac1 >> 2) * 4 + 1][ar1] = av1.y;
            As[(ac1 >> 2) * 4 + 2][ar1] = av1.z; As[(ac1 >> 2) * 4 + 3][ar1] = av1.w;
            Bs[(ac0 >> 2) * 4 + 0][ar0] = bv0.x; Bs[(ac0 >> 2) * 4 + 1][ar0] = bv0.y;
            Bs[(ac0 >> 2) * 4 + 2][ar0] = bv0.z; Bs[(ac0 >> 2) * 4 + 3][ar0] = bv0.w;
            Bs[(ac1 >> 2) * 4 + 0][ar1] = bv1.x; Bs[(ac1 >> 2) * 4 + 1][ar1] = bv1.y;
            Bs[(ac1 >> 2) * 4 + 2][ar1] = bv1.z; Bs[(ac1 >> 2) * 4 + 3][ar1] = bv1.w;
            __syncthreads();
        }
    }

    // epilogue
#pragma unroll
    for (int i = 0; i < 8; i++) {
        size_t r = (size_t)(row0 + ty * 8 + i);
        float* crow = C + r * (size_t)Ncols + col0 + tx * 8;
        float2 f0 = unpack2(c2[i][0]);
        float2 f1 = unpack2(c2[i][1]);
        float2 f2v = unpack2(c2[i][2]);
        float2 f3 = unpack2(c2[i][3]);
        float4 o0, o1;
        if (bias) {
            const float* bp = bias + col0 + tx * 8;
            o0 = make_float4(f0.x * scale + bp[0], f0.y * scale + bp[1],
                             f1.x * scale + bp[2], f1.y * scale + bp[3]);
            o1 = make_float4(f2v.x * scale + bp[4], f2v.y * scale + bp[5],
                             f3.x * scale + bp[6], f3.y * scale + bp[7]);
        } else {
            o0 = make_float4(f0.x * scale, f0.y * scale, f1.x * scale, f1.y * scale);
            o1 = make_float4(f2v.x * scale, f2v.y * scale, f3.x * scale, f3.y * scale);
        }
        *(float4*)&crow[0] = o0;
        *(float4*)&crow[4] = o1;
    }
}

// ---------------------------------------------------------------------------
// Pos-gate stream + fused epilogue.
// Tile: 4 n-rows x 256 m-cols per CTA (256 threads, 4 m-elems per thread).
// Streams PE plane-by-plane (e-major; each plane contiguous [N,M]).
// acc[h] per element via packed FFMA2; Wg pre-duplicated as f32x2 in SMEM.
// Epilogue: sigmoid(log(w)+aff) == w / (w + exp(-aff)); sum_h > 8 -> 1.
// ---------------------------------------------------------------------------
__global__ void __launch_bounds__(256)
pos_epilogue_kernel(const float* __restrict__ PE, const float* __restrict__ Wg_w,
                    const float* __restrict__ Wg_b, float* __restrict__ out)
{
    __shared__ ull sh_wg2[EMB][HEADS];   // dup'd f32x2 per (e, h)
    __shared__ float sh_b[HEADS];

    const int tid = threadIdx.x;
    for (int idx = tid; idx < EMB * HEADS; idx += 256) {
        int e = idx >> 4, h = idx & 15;
        sh_wg2[e][h] = dup2(Wg_w[h * EMB + e]);
    }
    if (tid < HEADS) sh_b[tid] = Wg_b[tid];
    __syncthreads();

    const int mlane = tid & 63;
    const int nrow  = tid >> 6;
    const int n = blockIdx.y * 4 + nrow;
    const int m = blockIdx.x * 256 + mlane * 4;

    // PE plane stride: NDIM*MDIM floats = (1<<22) floats = (1<<20) ulonglong2
    const ulonglong2* pe = (const ulonglong2*)(PE + (size_t)n * MDIM + m);

    ull acc2[HEADS][2];
#pragma unroll
    for (int h = 0; h < HEADS; h++) { acc2[h][0] = 0ull; acc2[h][1] = 0ull; }

    // software-pipelined streaming over the 64 embedding planes (depth 4)
    ulonglong2 buf[4];
#pragma unroll
    for (int i = 0; i < 4; i++) buf[i] = pe[(size_t)i << 20];

    for (int eo = 0; eo < EMB; eo += 4) {
#pragma unroll
        for (int i = 0; i < 4; i++) {
            ulonglong2 pv = buf[i];
            int en_ = eo + 4 + i;
            if (en_ < EMB) buf[i] = pe[(size_t)en_ << 20];
            const ulonglong2* wrow = (const ulonglong2*)sh_wg2[eo + i];
#pragma unroll
            for (int h2 = 0; h2 < 8; h2++) {
                ulonglong2 w = wrow[h2];
                fma2(acc2[h2 * 2][0],     w.x, pv.x);
                fma2(acc2[h2 * 2][1],     w.x, pv.y);
                fma2(acc2[h2 * 2 + 1][0], w.y, pv.x);
                fma2(acc2[h2 * 2 + 1][1], w.y, pv.y);
            }
        }
    }

    // epilogue: fused sigmoid-mean-threshold
    const float4 av = *(const float4*)&g_aff[(size_t)n * MDIM + m];
    const float L2E = 1.4426950408889634f;
    float en0 = exp2f(-av.x * L2E);
    float en1 = exp2f(-av.y * L2E);
    float en2 = exp2f(-av.z * L2E);
    float en3 = exp2f(-av.w * L2E);

    float s0 = 0.f, s1 = 0.f, s2 = 0.f, s3 = 0.f;
#pragma unroll
    for (int h = 0; h < HEADS; h++) {
        float bh = sh_b[h];
        float2 p0 = unpack2(acc2[h][0]);
        float2 p1 = unpack2(acc2[h][1]);
        float w;
        w = fmaxf(p0.x + bh, 0.f) + 1e-6f; s0 += __fdiv_rn(w, w + en0);
        w = fmaxf(p0.y + bh, 0.f) + 1e-6f; s1 += __fdiv_rn(w, w + en1);
        w = fmaxf(p1.x + bh, 0.f) + 1e-6f; s2 += __fdiv_rn(w, w + en2);
        w = fmaxf(p1.y + bh, 0.f) + 1e-6f; s3 += __fdiv_rn(w, w + en3);
    }

    float4 o;
    o.x = (s0 > 8.0f) ? 1.0f : 0.0f;
    o.y = (s1 > 8.0f) ? 1.0f : 0.0f;
    o.z = (s2 > 8.0f) ? 1.0f : 0.0f;
    o.w = (s3 > 8.0f) ? 1.0f : 0.0f;
    *(float4*)&out[(size_t)n * MDIM + m] = o;
}

// ---------------------------------------------------------------------------
extern "C" void kernel_launch(void* const* d_in, const int* in_sizes, int n_in,
                              void* d_out, int out_size)
{
    (void)in_sizes; (void)n_in; (void)out_size;
    const float* ref_feat = (const float*)d_in[0];
    const float* sup_feat = (const float*)d_in[1];
    const float* PE       = (const float*)d_in[2];
    const float* Wg_w     = (const float*)d_in[3];
    const float* Wg_b     = (const float*)d_in[4];
    const float* Wq_w     = (const float*)d_in[5];
    const float* Wq_b     = (const float*)d_in[6];
    const float* Wk_w     = (const float*)d_in[7];
    const float* Wk_b     = (const float*)d_in[8];
    float* out = (float*)d_out;

    // q = ref @ WqT + bq  : C [2048 x 1024]
    gemm_nt_kernel<<<dim3(DDIM / BN, NDIM / BM), 256>>>(ref_feat, Wq_w, Wq_b, DDIM, 1.0f, 0);
    // k = sup @ WkT + bk  : C [2048 x 1024]
    gemm_nt_kernel<<<dim3(DDIM / BN, MDIM / BM), 256>>>(sup_feat, Wk_w, Wk_b, DDIM, 1.0f, 1);
    // aff = (q @ kT) / 32 : C [2048 x 2048]
    gemm_nt_kernel<<<dim3(MDIM / BN, NDIM / BM), 256>>>(nullptr, nullptr, nullptr, MDIM, 0.03125f, 2);
    // pos stream + fused epilogue
    pos_epilogue_kernel<<<dim3(MDIM / 256, NDIM / 4), 256>>>(PE, Wg_w, Wg_b, out);
}

// round 3
// speedup vs baseline: 1.1483x; 1.1483x over previous
#include <cuda_runtime.h>
#include <cstdint>

// ---------------------------------------------------------------------------
// AdjGenerator: adj = (mean_h sigmoid(log(relu(Wg·PE)+1e-6) + (q·kT)/32) > 0.5)
// N = M = 2048, D = 1024, EMB = 64, HEADS = 16
// ---------------------------------------------------------------------------

#define NDIM 2048
#define MDIM 2048
#define DDIM 1024
#define EMB  64
#define HEADS 16

__device__ float g_q[NDIM * DDIM];
__device__ float g_k[MDIM * DDIM];
__device__ float g_aff[NDIM * MDIM];

typedef unsigned long long ull;

// ---- packed f32x2 helpers (Blackwell FFMA2, PTX-only) ---------------------
__device__ __forceinline__ ull dup2(float v) {
    ull r;
    asm("mov.b64 %0, {%1, %1};" : "=l"(r) : "f"(v));
    return r;
}
__device__ __forceinline__ void fma2(ull& d, ull a, ull b) {
    asm("fma.rn.f32x2 %0, %1, %2, %0;" : "+l"(d) : "l"(a), "l"(b));
}
__device__ __forceinline__ float2 unpack2(ull v) {
    float2 f;
    asm("mov.b64 {%0, %1}, %2;" : "=f"(f.x), "=f"(f.y) : "l"(v));
    return f;
}

// ---------------------------------------------------------------------------
// SGEMM NT: C[r,c] = scale * sum_d A[r,d]*B[c,d] + bias[c]
// BM=BN=128, BK=16, 256 threads, 8x8 per thread.
// A-tile stored PRE-DUPLICATED as f32x2 in SMEM (no dup movs in inner loop).
// ---------------------------------------------------------------------------
#define BM 128
#define BN 128
#define BK 16

__global__ void __launch_bounds__(256, 2)
gemm_nt_kernel(const float* __restrict__ A, const float* __restrict__ B,
               const float* __restrict__ bias, int Ncols, float scale, int outsel)
{
    float* C;
    if (outsel == 0)      C = g_q;
    else if (outsel == 1) C = g_k;
    else { C = g_aff; A = g_q; B = g_k; }

    const int K = DDIM;

    __shared__ ull   Asd[BK][BM];        // duplicated f32x2 per a-value (16 KB)
    __shared__ float Bs[BK][BN + 4];

    const int tid = threadIdx.x;
    const int tx = tid & 15;
    const int ty = tid >> 4;
    const int row0 = blockIdx.y * BM;
    const int col0 = blockIdx.x * BN;

    const float* Abase = A + (size_t)row0 * K;
    const float* Bbase = B + (size_t)col0 * K;

    const int ar0 = tid >> 2,          ac0 = (tid & 3) * 4;
    const int ar1 = (tid + 256) >> 2,  ac1 = ((tid + 256) & 3) * 4;

    float4 av0 = *(const float4*)&Abase[(size_t)ar0 * K + ac0];
    float4 av1 = *(const float4*)&Abase[(size_t)ar1 * K + ac1];
    float4 bv0 = *(const float4*)&Bbase[(size_t)ar0 * K + ac0];
    float4 bv1 = *(const float4*)&Bbase[(size_t)ar1 * K + ac1];

    Asd[ac0 + 0][ar0] = dup2(av0.x); Asd[ac0 + 1][ar0] = dup2(av0.y);
    Asd[ac0 + 2][ar0] = dup2(av0.z); Asd[ac0 + 3][ar0] = dup2(av0.w);
    Asd[ac1 + 0][ar1] = dup2(av1.x); Asd[ac1 + 1][ar1] = dup2(av1.y);
    Asd[ac1 + 2][ar1] = dup2(av1.z); Asd[ac1 + 3][ar1] = dup2(av1.w);
    Bs[ac0 + 0][ar0] = bv0.x; Bs[ac0 + 1][ar0] = bv0.y;
    Bs[ac0 + 2][ar0] = bv0.z; Bs[ac0 + 3][ar0] = bv0.w;
    Bs[ac1 + 0][ar1] = bv1.x; Bs[ac1 + 1][ar1] = bv1.y;
    Bs[ac1 + 2][ar1] = bv1.z; Bs[ac1 + 3][ar1] = bv1.w;
    __syncthreads();

    ull c2[8][4];
#pragma unroll
    for (int i = 0; i < 8; i++)
#pragma unroll
        for (int j = 0; j < 4; j++) c2[i][j] = 0ull;

    for (int kc = BK; kc <= K; kc += BK) {
        if (kc < K) {
            av0 = *(const float4*)&Abase[(size_t)ar0 * K + kc + ac0];
            av1 = *(const float4*)&Abase[(size_t)ar1 * K + kc + ac1];
            bv0 = *(const float4*)&Bbase[(size_t)ar0 * K + kc + ac0];
            bv1 = *(const float4*)&Bbase[(size_t)ar1 * K + kc + ac1];
        }
#pragma unroll
        for (int k = 0; k < BK; k++) {
            ulonglong2 a01 = *(const ulonglong2*)&Asd[k][ty * 8];
            ulonglong2 a23 = *(const ulonglong2*)&Asd[k][ty * 8 + 2];
            ulonglong2 a45 = *(const ulonglong2*)&Asd[k][ty * 8 + 4];
            ulonglong2 a67 = *(const ulonglong2*)&Asd[k][ty * 8 + 6];
            ull a2[8] = { a01.x, a01.y, a23.x, a23.y, a45.x, a45.y, a67.x, a67.y };
            ulonglong2 b01 = *(const ulonglong2*)&Bs[k][tx * 8];
            ulonglong2 b23 = *(const ulonglong2*)&Bs[k][tx * 8 + 4];
            ull b2[4] = { b01.x, b01.y, b23.x, b23.y };
#pragma unroll
            for (int i = 0; i < 8; i++) {
#pragma unroll
                for (int j = 0; j < 4; j++) fma2(c2[i][j], a2[i], b2[j]);
            }
        }
        if (kc < K) {
            __syncthreads();
            Asd[ac0 + 0][ar0] = dup2(av0.x); Asd[ac0 + 1][ar0] = dup2(av0.y);
            Asd[ac0 + 2][ar0] = dup2(av0.z); Asd[ac0 + 3][ar0] = dup2(av0.w);
            Asd[ac1 + 0][ar1] = dup2(av1.x); Asd[ac1 + 1][ar1] = dup2(av1.y);
            Asd[ac1 + 2][ar1] = dup2(av1.z); Asd[ac1 + 3][ar1] = dup2(av1.w);
            Bs[ac0 + 0][ar0] = bv0.x; Bs[ac0 + 1][ar0] = bv0.y;
            Bs[ac0 + 2][ar0] = bv0.z; Bs[ac0 + 3][ar0] = bv0.w;
            Bs[ac1 + 0][ar1] = bv1.x; Bs[ac1 + 1][ar1] = bv1.y;
            Bs[ac1 + 2][ar1] = bv1.z; Bs[ac1 + 3][ar1] = bv1.w;
            __syncthreads();
        }
    }

#pragma unroll
    for (int i = 0; i < 8; i++) {
        size_t r = (size_t)(row0 + ty * 8 + i);
        float* crow = C + r * (size_t)Ncols + col0 + tx * 8;
        float2 f0 = unpack2(c2[i][0]);
        float2 f1 = unpack2(c2[i][1]);
        float2 f2v = unpack2(c2[i][2]);
        float2 f3 = unpack2(c2[i][3]);
        float4 o0, o1;
        if (bias) {
            const float* bp = bias + col0 + tx * 8;
            o0 = make_float4(f0.x * scale + bp[0], f0.y * scale + bp[1],
                             f1.x * scale + bp[2], f1.y * scale + bp[3]);
            o1 = make_float4(f2v.x * scale + bp[4], f2v.y * scale + bp[5],
                             f3.x * scale + bp[6], f3.y * scale + bp[7]);
        } else {
            o0 = make_float4(f0.x * scale, f0.y * scale, f1.x * scale, f1.y * scale);
            o1 = make_float4(f2v.x * scale, f2v.y * scale, f3.x * scale, f3.y * scale);
        }
        *(float4*)&crow[0] = o0;
        *(float4*)&crow[4] = o1;
    }
}

// ---------------------------------------------------------------------------
// Pos-gate stream + fused epilogue — occupancy-optimized.
// Each thread: 2 m-elements (1 packed f32x2 acc per head = 16 ull = 32 regs).
// CTA = 256 threads covers 1 n-row x 512 m. Prefetch depth 8 (8 LDG.64
// in flight per thread). PE streamed once -> __ldcs evict-first.
// sigmoid(log(w)+aff) == w / (w + exp(-aff));  sum_h > 8 -> 1.
// ---------------------------------------------------------------------------
__global__ void __launch_bounds__(256, 3)
pos_epilogue_kernel(const float* __restrict__ PE, const float* __restrict__ Wg_w,
                    const float* __restrict__ Wg_b, float* __restrict__ out)
{
    __shared__ ull sh_wg2[EMB][HEADS];   // dup'd f32x2 per (e, h)
    __shared__ float sh_b[HEADS];

    const int tid = threadIdx.x;
    for (int idx = tid; idx < EMB * HEADS; idx += 256) {
        int e = idx >> 4, h = idx & 15;
        sh_wg2[e][h] = dup2(Wg_w[h * EMB + e]);
    }
    if (tid < HEADS) sh_b[tid] = Wg_b[tid];
    __syncthreads();

    const int n = blockIdx.y;
    const int m = blockIdx.x * 512 + tid * 2;

    // plane stride: NDIM*MDIM floats = 2^22 floats = 2^21 ull
    const ull* pe = (const ull*)PE + (((size_t)n * MDIM + m) >> 1);

    ull acc[HEADS];
#pragma unroll
    for (int h = 0; h < HEADS; h++) acc[h] = 0ull;

    ull buf[8];
#pragma unroll
    for (int i = 0; i < 8; i++) buf[i] = __ldcs(pe + ((size_t)i << 21));

    for (int eo = 0; eo < EMB; eo += 8) {
#pragma unroll
        for (int i = 0; i < 8; i++) {
            ull pv = buf[i];
            int en_ = eo + 8 + i;
            if (en_ < EMB) buf[i] = __ldcs(pe + ((size_t)en_ << 21));
            const ulonglong2* wrow = (const ulonglong2*)sh_wg2[eo + i];
#pragma unroll
            for (int h2 = 0; h2 < 8; h2++) {
                ulonglong2 w = wrow[h2];
                fma2(acc[2 * h2],     w.x, pv);
                fma2(acc[2 * h2 + 1], w.y, pv);
            }
        }
    }

    // fused sigmoid-mean-threshold
    const float2 av = *(const float2*)&g_aff[(size_t)n * MDIM + m];
    const float L2E = 1.4426950408889634f;
    float en0 = exp2f(-av.x * L2E);
    float en1 = exp2f(-av.y * L2E);

    float s0 = 0.f, s1 = 0.f;
#pragma unroll
    for (int h = 0; h < HEADS; h++) {
        float bh = sh_b[h];
        float2 p = unpack2(acc[h]);
        float w0 = fmaxf(p.x + bh, 0.f) + 1e-6f; s0 += __fdividef(w0, w0 + en0);
        float w1 = fmaxf(p.y + bh, 0.f) + 1e-6f; s1 += __fdividef(w1, w1 + en1);
    }

    float2 o;
    o.x = (s0 > 8.0f) ? 1.0f : 0.0f;
    o.y = (s1 > 8.0f) ? 1.0f : 0.0f;
    *(float2*)&out[(size_t)n * MDIM + m] = o;
}

// ---------------------------------------------------------------------------
extern "C" void kernel_launch(void* const* d_in, const int* in_sizes, int n_in,
                              void* d_out, int out_size)
{
    (void)in_sizes; (void)n_in; (void)out_size;
    const float* ref_feat = (const float*)d_in[0];
    const float* sup_feat = (const float*)d_in[1];
    const float* PE       = (const float*)d_in[2];
    const float* Wg_w     = (const float*)d_in[3];
    const float* Wg_b     = (const float*)d_in[4];
    const float* Wq_w     = (const float*)d_in[5];
    const float* Wq_b     = (const float*)d_in[6];
    const float* Wk_w     = (const float*)d_in[7];
    const float* Wk_b     = (const float*)d_in[8];
    float* out = (float*)d_out;

    gemm_nt_kernel<<<dim3(DDIM / BN, NDIM / BM), 256>>>(ref_feat, Wq_w, Wq_b, DDIM, 1.0f, 0);
    gemm_nt_kernel<<<dim3(DDIM / BN, MDIM / BM), 256>>>(sup_feat, Wk_w, Wk_b, DDIM, 1.0f, 1);
    gemm_nt_kernel<<<dim3(MDIM / BN, NDIM / BM), 256>>>(nullptr, nullptr, nullptr, MDIM, 0.03125f, 2);
    pos_epilogue_kernel<<<dim3(MDIM / 512, NDIM), 256>>>(PE, Wg_w, Wg_b, out);
}